// round 10
// baseline (speedup 1.0000x reference)
#include <cuda_runtime.h>
#include <math.h>

#define BB   256
#define HH   32
#define WW   32
#define AA   5
#define NCC  20
#define MM   50
#define NOBJ (BB*MM)

#define GRID    1280                   // 128-thr blocks; ~10 blocks/SM, 1 wave
#define NTHR    128
#define NF4     (BB*AA*256)            // 327680 conf float4s = GRID*NTHR*2
#define HALF    (GRID*NTHR)            // 163840
#define OPB     10                     // 1280*10 = 12800 objects exactly

// Zero-init at load; last block resets accumulators each launch -> replay-safe.
__device__ float    g_acc[4];
__device__ unsigned g_cnt;

__device__ __forceinline__ float sigm(float x) { return 1.0f / (1.0f + __expf(-x)); }

__device__ __forceinline__ const float4* conf_ptr(const float4* out4, int t) {
    int b = t / (AA * 256);
    int r = t - b * (AA * 256);
    int a = r >> 8;
    int q = r & 255;
    return out4 + (size_t)(b * 125 + a * 25 + NCC) * 256 + q;
}

__global__ void __launch_bounds__(128, 10)
fused_loss_kernel(const float* __restrict__ out,
                  const float4* __restrict__ gt_boxes,
                  const float* __restrict__ anchor,
                  const int* __restrict__ gt_classes,
                  const int* __restrict__ num_box,
                  float* __restrict__ dout) {
    __shared__ int    s_cell[2 * MM];
    __shared__ int    s_cls [2 * MM];
    __shared__ int    s_meta[OPB];      // packed b | cell<<8 | cls<<18
    __shared__ float4 s_box [OPB];      // tx,ty,tw,th (already *32)
    __shared__ int    s_nrec;
    __shared__ float  sm[4][4];

    int tid  = threadIdx.x;
    int lane = tid & 31;
    int wid  = tid >> 5;
    float boxl = 0.0f, confl = 0.0f, noobj = 0.0f, clsl = 0.0f;

    // ---- front-batched dense loads: in flight during phases 0-2 ----
    int gid = blockIdx.x * NTHR + tid;
    const float4* out4 = (const float4*)out;
    float4 v0 = *conf_ptr(out4, gid);
    float4 v1 = *conf_ptr(out4, gid + HALF);

    int i0 = blockIdx.x * OPB;
    int b0 = i0 / MM;

    // ---- phase 0: cells/classes of this block's (<=2) batches into smem ----
    if (tid == 0) s_nrec = 0;
    if (tid < 2 * MM) {
        int bb = b0 + tid / MM;
        int m2 = tid % MM;
        int cellv = -1, clsv = 0;
        if (bb < BB) {
            int nb = num_box[bb]; if (nb > MM) nb = MM;
            if (m2 < nb) {
                float4 bx = gt_boxes[bb * MM + m2];
                int gx = (int)(bx.x * 32.0f);
                int gy = (int)(bx.y * 32.0f);
                cellv = gy * WW + gx;
                clsv  = gt_classes[bb * MM + m2];
            }
        }
        s_cell[tid] = cellv;
        s_cls [tid] = clsv;
    }
    __syncthreads();

    // ---- phase 1: winner scan over smem + compaction (lanes 0-9, warp 0) ----
    if (tid < OPB) {
        int i = i0 + tid;
        int bb = i / MM;
        int m  = i - bb * MM;
        int base = (bb - b0) * MM;
        int mycell = s_cell[base + m];
        if (mycell >= 0) {
            int last = -1, minc = 1 << 30;
            #pragma unroll
            for (int m2 = 0; m2 < MM; m2++) {
                int c2 = s_cell[base + m2];
                if (c2 == mycell) {
                    last = m2;
                    int cc = s_cls[base + m2];
                    minc = (cc < minc) ? cc : minc;
                }
            }
            if (last == m) {
                int r = atomicAdd(&s_nrec, 1);
                s_meta[r] = bb | (mycell << 8) | (minc << 18);
                float4 bx = gt_boxes[i];
                s_box[r] = make_float4(bx.x * 32.0f, bx.y * 32.0f,
                                       bx.z * 32.0f, bx.w * 32.0f);
            }
        }
    }
    __syncthreads();

    // ---- phase 2: warp-cooperative winner processing (4 warps round-robin) ----
    {
        const unsigned FULL = 0xffffffffu;
        int a_id = lane / 5, ch = lane - a_id * 5;
        float anc = 1.0f;
        if (lane < 25 && ch >= 3) anc = anchor[2 * a_id + (ch - 3)];
        int nrec = s_nrec;
        for (int r = wid; r < nrec; r += 4) {
            int   meta = s_meta[r];
            float4 tb  = s_box[r];
            int bb   = meta & 255;
            int cell = (meta >> 8) & 1023;
            int cls  = (meta >> 18) & 31;
            const float* cellb = out + (size_t)bb * 128000 + cell;
            int wq = cell & 31, hq = (cell >> 5) & 31;

            // one LDG: 25 anchor-stat values in flight at once
            float v = 0.0f;
            if (lane < 25) v = cellb[(a_id * 25 + NCC + ch) * 1024];
            float tval = (ch <= 2) ? sigm(v) : __expf(v) * anc;
            float s1 = __shfl_sync(FULL, tval, lane + 1);
            float s2 = __shfl_sync(FULL, tval, lane + 2);
            float s3 = __shfl_sync(FULL, tval, lane + 3);
            float s4 = __shfl_sync(FULL, tval, lane + 4);

            float tx = tb.x, ty = tb.y, tw = tb.z, th = tb.w;
            float tx1 = tx - tw * 0.5f, ty1 = ty - th * 0.5f;
            float tx2 = tx + tw * 0.5f, ty2 = ty + th * 0.5f;
            float tarea = tw * th;

            float iou = -2.0f, px = 0, py = 0, pw = 0, ph = 0, pconf = 0;
            if (lane < 25 && ch == 0) {               // anchor-lead lanes
                pconf = tval;
                px = (float)wq + s1; py = (float)hq + s2;
                pw = s3; ph = s4;
                float ax1 = px - pw * 0.5f, ay1 = py - ph * 0.5f;
                float ax2 = px + pw * 0.5f, ay2 = py + ph * 0.5f;
                float iw = fmaxf(fminf(ax2, tx2) - fmaxf(ax1, tx1), 0.0f);
                float ih = fmaxf(fminf(ay2, ty2) - fmaxf(ay1, ty1), 0.0f);
                float inter = iw * ih;
                float uni = pw * ph + tarea - inter;
                iou = inter / fmaxf(uni, 1e-10f);
            }
            float bi = -1.0f; int best = 0;
            float bx = 0, by = 0, bw = 0, bh = 0, pcb = 0;
            #pragma unroll
            for (int a = 0; a < AA; a++) {
                float ia = __shfl_sync(FULL, iou,   a * 5);
                float xa = __shfl_sync(FULL, px,    a * 5);
                float ya = __shfl_sync(FULL, py,    a * 5);
                float wa = __shfl_sync(FULL, pw,    a * 5);
                float ha = __shfl_sync(FULL, ph,    a * 5);
                float ca = __shfl_sync(FULL, pconf, a * 5);
                if (ia > bi) { bi = ia; best = a; bx = xa; by = ya; bw = wa; bh = ha; pcb = ca; }
            }

            // one LDG: the best anchor's 20 class logits; shfl softmax
            float lv = (lane < NCC) ? cellb[(best * 25 + lane) * 1024] : -1e30f;
            float mx = lv;
            #pragma unroll
            for (int o = 16; o > 0; o >>= 1)
                mx = fmaxf(mx, __shfl_xor_sync(FULL, mx, o));
            float ex = (lane < NCC) ? __expf(lv - mx) : 0.0f;
            #pragma unroll
            for (int o = 16; o > 0; o >>= 1)
                ex += __shfl_xor_sync(FULL, ex, o);
            float lc = __shfl_sync(FULL, lv, cls);

            if (lane == 0) {
                float d0 = bx - tx, d1 = by - ty;
                float d2 = sqrtf(bw) - sqrtf(tw), d3 = sqrtf(bh) - sqrtf(th);
                boxl  += d0 * d0 + d1 * d1 + d2 * d2 + d3 * d3;
                confl += (pcb - 1.0f) * (pcb - 1.0f);
                noobj -= pcb * pcb;                    // remove best from noobj
                clsl  += mx + __logf(ex) - lc;
            }
        }
    }

    // ---- consume the front-batched dense loads ----
    {
        float s;
        s = sigm(v0.x); noobj += s * s;
        s = sigm(v0.y); noobj += s * s;
        s = sigm(v0.z); noobj += s * s;
        s = sigm(v0.w); noobj += s * s;
        s = sigm(v1.x); noobj += s * s;
        s = sigm(v1.y); noobj += s * s;
        s = sigm(v1.z); noobj += s * s;
        s = sigm(v1.w); noobj += s * s;
    }

    // ---- block reduction (4 warps) ----
    #pragma unroll
    for (int off = 16; off > 0; off >>= 1) {
        boxl  += __shfl_down_sync(0xffffffffu, boxl,  off);
        confl += __shfl_down_sync(0xffffffffu, confl, off);
        noobj += __shfl_down_sync(0xffffffffu, noobj, off);
        clsl  += __shfl_down_sync(0xffffffffu, clsl,  off);
    }
    if (lane == 0) {
        sm[0][wid] = boxl; sm[1][wid] = confl;
        sm[2][wid] = noobj; sm[3][wid] = clsl;
    }
    __syncthreads();
    if (tid == 0) {
        float s0 = 0, s1 = 0, s2 = 0, s3 = 0;
        #pragma unroll
        for (int k = 0; k < 4; k++) {
            s0 += sm[0][k]; s1 += sm[1][k]; s2 += sm[2][k]; s3 += sm[3][k];
        }
        if (s0 != 0.0f) atomicAdd(&g_acc[0], s0);
        if (s1 != 0.0f) atomicAdd(&g_acc[1], s1);
        atomicAdd(&g_acc[2], s2);
        if (s3 != 0.0f) atomicAdd(&g_acc[3], s3);
        __threadfence();
        unsigned old = atomicInc(&g_cnt, GRID - 1);
        if (old == GRID - 1) {                  // last block finalizes
            volatile float* a = g_acc;
            dout[0] = a[0] * (5.0f / 256.0f);   // LAM_COORD / B
            dout[1] = a[1] * (1.0f / 256.0f);   // LAM_OBJ   / B
            dout[2] = a[2] * (0.5f / 256.0f);   // LAM_NOOBJ / B
            dout[3] = a[3] * (1.0f / 256.0f);   // LAM_CLS   / B
            g_acc[0] = 0.0f; g_acc[1] = 0.0f;   // reset for next replay
            g_acc[2] = 0.0f; g_acc[3] = 0.0f;
        }
    }
}

extern "C" void kernel_launch(void* const* d_in, const int* in_sizes, int n_in,
                              void* d_out, int out_size) {
    const float*  out_t      = (const float*)d_in[0];
    const float4* gt_boxes   = (const float4*)d_in[1];
    const float*  anchor     = (const float*)d_in[2];
    const int*    gt_classes = (const int*)d_in[3];
    const int*    num_box    = (const int*)d_in[4];
    float* dout = (float*)d_out;

    fused_loss_kernel<<<GRID, NTHR>>>(out_t, gt_boxes, anchor,
                                      gt_classes, num_box, dout);
}

// round 11
// speedup vs baseline: 1.0280x; 1.0280x over previous
#include <cuda_runtime.h>
#include <math.h>

#define BB   256
#define HH   32
#define WW   32
#define AA   5
#define NCC  20
#define MM   50
#define NOBJ (BB*MM)

#define GRID    1280                   // 128-thr blocks; 5 blocks per batch
#define NTHR    128
#define NF4     (BB*AA*256)            // 327680 conf float4s = GRID*NTHR*2
#define HALF    (GRID*NTHR)            // 163840
#define OPB     10                     // 1280*10 = 12800; one batch per block

// Zero-init at load; last block resets accumulators each launch -> replay-safe.
__device__ float    g_acc[4];
__device__ unsigned g_cnt;

__device__ __forceinline__ float sigm(float x) { return 1.0f / (1.0f + __expf(-x)); }

__device__ __forceinline__ const float4* conf_ptr(const float4* out4, int t) {
    int b = t / (AA * 256);
    int r = t - b * (AA * 256);
    int a = r >> 8;
    int q = r & 255;
    return out4 + (size_t)(b * 125 + a * 25 + NCC) * 256 + q;
}

__global__ void __launch_bounds__(128, 10)
fused_loss_kernel(const float* __restrict__ out,
                  const float4* __restrict__ gt_boxes,
                  const float* __restrict__ anchor,
                  const int* __restrict__ gt_classes,
                  const int* __restrict__ num_box,
                  float* __restrict__ dout) {
    __shared__ int    s_cell[MM];       // this block's single batch
    __shared__ int    s_cls [MM];
    __shared__ float4 s_gt  [MM];
    __shared__ int    s_meta[OPB];      // packed cell | cls<<10
    __shared__ float4 s_box [OPB];      // tx,ty,tw,th (already *32)
    __shared__ int    s_nrec;
    __shared__ float  sm[4][4];

    int tid  = threadIdx.x;
    int lane = tid & 31;
    int wid  = tid >> 5;
    float boxl = 0.0f, confl = 0.0f, noobj = 0.0f, clsl = 0.0f;

    int bb    = blockIdx.x / 5;         // batch of this block
    int mbase = (blockIdx.x % 5) * OPB; // object sub-range within the batch

    // ---- issue dense loads + phase-0 gt loads; all overlap ----
    int gid = blockIdx.x * NTHR + tid;
    const float4* out4 = (const float4*)out;
    float4 v0 = *conf_ptr(out4, gid);
    float4 v1 = *conf_ptr(out4, gid + HALF);

    if (tid == 0) s_nrec = 0;
    int nb = num_box[bb]; if (nb > MM) nb = MM;
    float4 gtb; int clv = 0;
    if (tid < MM) {
        gtb = gt_boxes[bb * MM + tid];
        clv = gt_classes[bb * MM + tid];
    }

    // ---- consume dense loads while the gt LDGs are still in flight ----
    {
        float s;
        s = sigm(v0.x); noobj += s * s;
        s = sigm(v0.y); noobj += s * s;
        s = sigm(v0.z); noobj += s * s;
        s = sigm(v0.w); noobj += s * s;
        s = sigm(v1.x); noobj += s * s;
        s = sigm(v1.y); noobj += s * s;
        s = sigm(v1.z); noobj += s * s;
        s = sigm(v1.w); noobj += s * s;
    }

    // ---- phase 0: store cells/classes/boxes of the batch to smem ----
    if (tid < MM) {
        int cellv = -1;
        if (tid < nb) {
            int gx = (int)(gtb.x * 32.0f);
            int gy = (int)(gtb.y * 32.0f);
            cellv = gy * WW + gx;
        }
        s_cell[tid] = cellv;
        s_cls [tid] = clv;
        s_gt  [tid] = gtb;
    }
    __syncthreads();

    // ---- phase 1: winner check for this block's 10 objects + compaction ----
    if (tid < OPB) {
        int m = mbase + tid;
        int mycell = (m < MM) ? s_cell[m] : -1;
        if (mycell >= 0) {
            int last = -1, minc = 1 << 30;
            #pragma unroll
            for (int m2 = 0; m2 < MM; m2++) {
                int c2 = s_cell[m2];
                if (c2 == mycell) {
                    last = m2;
                    int cc = s_cls[m2];
                    minc = (cc < minc) ? cc : minc;
                }
            }
            if (last == m) {
                int r = atomicAdd(&s_nrec, 1);
                s_meta[r] = mycell | (minc << 10);
                float4 bx = s_gt[m];
                s_box[r] = make_float4(bx.x * 32.0f, bx.y * 32.0f,
                                       bx.z * 32.0f, bx.w * 32.0f);
            }
        }
    }
    __syncthreads();

    // ---- phase 2: warp-cooperative winner processing (4 warps round-robin) ----
    {
        const unsigned FULL = 0xffffffffu;
        int a_id = lane / 5, ch = lane - a_id * 5;
        float anc = 1.0f;
        if (lane < 25 && ch >= 3) anc = anchor[2 * a_id + (ch - 3)];
        int nrec = s_nrec;
        const float* batb = out + (size_t)bb * 128000;
        for (int r = wid; r < nrec; r += 4) {
            int   meta = s_meta[r];
            float4 tb  = s_box[r];
            int cell = meta & 1023;
            int cls  = meta >> 10;
            const float* cellb = batb + cell;
            int wq = cell & 31, hq = (cell >> 5) & 31;

            // one LDG: 25 anchor-stat values in flight at once
            float v = 0.0f;
            if (lane < 25) v = cellb[(a_id * 25 + NCC + ch) * 1024];
            float tval = (ch <= 2) ? sigm(v) : __expf(v) * anc;
            float s1 = __shfl_sync(FULL, tval, lane + 1);
            float s2 = __shfl_sync(FULL, tval, lane + 2);
            float s3 = __shfl_sync(FULL, tval, lane + 3);
            float s4 = __shfl_sync(FULL, tval, lane + 4);

            float tx = tb.x, ty = tb.y, tw = tb.z, th = tb.w;
            float tx1 = tx - tw * 0.5f, ty1 = ty - th * 0.5f;
            float tx2 = tx + tw * 0.5f, ty2 = ty + th * 0.5f;
            float tarea = tw * th;

            float iou = -2.0f, px = 0, py = 0, pw = 0, ph = 0, pconf = 0;
            if (lane < 25 && ch == 0) {               // anchor-lead lanes
                pconf = tval;
                px = (float)wq + s1; py = (float)hq + s2;
                pw = s3; ph = s4;
                float ax1 = px - pw * 0.5f, ay1 = py - ph * 0.5f;
                float ax2 = px + pw * 0.5f, ay2 = py + ph * 0.5f;
                float iw = fmaxf(fminf(ax2, tx2) - fmaxf(ax1, tx1), 0.0f);
                float ih = fmaxf(fminf(ay2, ty2) - fmaxf(ay1, ty1), 0.0f);
                float inter = iw * ih;
                float uni = pw * ph + tarea - inter;
                iou = inter / fmaxf(uni, 1e-10f);
            }
            float bi = -1.0f; int best = 0;
            float bx = 0, by = 0, bw = 0, bh = 0, pcb = 0;
            #pragma unroll
            for (int a = 0; a < AA; a++) {
                float ia = __shfl_sync(FULL, iou,   a * 5);
                float xa = __shfl_sync(FULL, px,    a * 5);
                float ya = __shfl_sync(FULL, py,    a * 5);
                float wa = __shfl_sync(FULL, pw,    a * 5);
                float ha = __shfl_sync(FULL, ph,    a * 5);
                float ca = __shfl_sync(FULL, pconf, a * 5);
                if (ia > bi) { bi = ia; best = a; bx = xa; by = ya; bw = wa; bh = ha; pcb = ca; }
            }

            // one LDG: the best anchor's 20 class logits; shfl softmax
            float lv = (lane < NCC) ? cellb[(best * 25 + lane) * 1024] : -1e30f;
            float mx = lv;
            #pragma unroll
            for (int o = 16; o > 0; o >>= 1)
                mx = fmaxf(mx, __shfl_xor_sync(FULL, mx, o));
            float ex = (lane < NCC) ? __expf(lv - mx) : 0.0f;
            #pragma unroll
            for (int o = 16; o > 0; o >>= 1)
                ex += __shfl_xor_sync(FULL, ex, o);
            float lc = __shfl_sync(FULL, lv, cls);

            if (lane == 0) {
                float d0 = bx - tx, d1 = by - ty;
                float d2 = sqrtf(bw) - sqrtf(tw), d3 = sqrtf(bh) - sqrtf(th);
                boxl  += d0 * d0 + d1 * d1 + d2 * d2 + d3 * d3;
                confl += (pcb - 1.0f) * (pcb - 1.0f);
                noobj -= pcb * pcb;                    // remove best from noobj
                clsl  += mx + __logf(ex) - lc;
            }
        }
    }

    // ---- block reduction (4 warps) ----
    #pragma unroll
    for (int off = 16; off > 0; off >>= 1) {
        boxl  += __shfl_down_sync(0xffffffffu, boxl,  off);
        confl += __shfl_down_sync(0xffffffffu, confl, off);
        noobj += __shfl_down_sync(0xffffffffu, noobj, off);
        clsl  += __shfl_down_sync(0xffffffffu, clsl,  off);
    }
    if (lane == 0) {
        sm[0][wid] = boxl; sm[1][wid] = confl;
        sm[2][wid] = noobj; sm[3][wid] = clsl;
    }
    __syncthreads();
    if (tid == 0) {
        float s0 = 0, s1 = 0, s2 = 0, s3 = 0;
        #pragma unroll
        for (int k = 0; k < 4; k++) {
            s0 += sm[0][k]; s1 += sm[1][k]; s2 += sm[2][k]; s3 += sm[3][k];
        }
        if (s0 != 0.0f) atomicAdd(&g_acc[0], s0);
        if (s1 != 0.0f) atomicAdd(&g_acc[1], s1);
        atomicAdd(&g_acc[2], s2);
        if (s3 != 0.0f) atomicAdd(&g_acc[3], s3);
        __threadfence();
        unsigned old = atomicInc(&g_cnt, GRID - 1);
        if (old == GRID - 1) {                  // last block finalizes
            volatile float* a = g_acc;
            dout[0] = a[0] * (5.0f / 256.0f);   // LAM_COORD / B
            dout[1] = a[1] * (1.0f / 256.0f);   // LAM_OBJ   / B
            dout[2] = a[2] * (0.5f / 256.0f);   // LAM_NOOBJ / B
            dout[3] = a[3] * (1.0f / 256.0f);   // LAM_CLS   / B
            g_acc[0] = 0.0f; g_acc[1] = 0.0f;   // reset for next replay
            g_acc[2] = 0.0f; g_acc[3] = 0.0f;
        }
    }
}

extern "C" void kernel_launch(void* const* d_in, const int* in_sizes, int n_in,
                              void* d_out, int out_size) {
    const float*  out_t      = (const float*)d_in[0];
    const float4* gt_boxes   = (const float4*)d_in[1];
    const float*  anchor     = (const float*)d_in[2];
    const int*    gt_classes = (const int*)d_in[3];
    const int*    num_box    = (const int*)d_in[4];
    float* dout = (float*)d_out;

    fused_loss_kernel<<<GRID, NTHR>>>(out_t, gt_boxes, anchor,
                                      gt_classes, num_box, dout);
}